// round 12
// baseline (speedup 1.0000x reference)
#include <cuda_runtime.h>
#include <cuda_bf16.h>
#include <cuda_fp16.h>
#include <math.h>
#include <stdint.h>

#define BB 2
#define SS 2048
#define DD 1024
#define HH 16
#define HD 64
#define ROWS (BB*SS)      // 4096
#define TRIPLE (3*HD)     // 192 halves per (row, head)
#define GK 1024           // GEMM K dim (fixed)

// ---------------------------------------------------------------------------
// Scratch (static device globals; no allocation at runtime)
// ---------------------------------------------------------------------------
__device__ __half g_qkvh[(size_t)ROWS * 3 * DD];      // fused qkv fp16 [row][3072]
__device__ __half g_ah[(size_t)ROWS * DD];            // inputs fp16 [row][K]
__device__ __half g_ch[(size_t)ROWS * DD];            // attn out fp16 [row][D]
__device__ __half g_wT[(size_t)3 * DD * DD];          // W_in^T fp16 [3072][1024]
__device__ __half g_oT[(size_t)DD * DD];              // W_out^T fp16 [1024][1024]
// flash operands (fp16): Q,K [bh][S][64]; V^T [bh][64][S]
__device__ __half g_qh[(size_t)BB * HH * SS * HD];
__device__ __half g_kh[(size_t)BB * HH * SS * HD];
__device__ __half g_vt[(size_t)BB * HH * HD * SS];

// ---------------------------------------------------------------------------
// PTX helpers (portable: mma.sync / ldmatrix / cp.async — no arch-'a' features)
// ---------------------------------------------------------------------------
__device__ __forceinline__ uint32_t smem_to_u32(const void* smem_ptr) {
    uint32_t addr;
    asm("{ .reg .u64 tmp; cvta.to.shared.u64 tmp, %1; cvt.u32.u64 %0, tmp; }"
        : "=r"(addr) : "l"(smem_ptr));
    return addr;
}
__device__ __forceinline__ void ldsm4(uint32_t* r, uint32_t addr) {
    asm volatile("ldmatrix.sync.aligned.m8n8.x4.shared.b16 {%0,%1,%2,%3}, [%4];"
                 : "=r"(r[0]), "=r"(r[1]), "=r"(r[2]), "=r"(r[3]) : "r"(addr));
}
__device__ __forceinline__ void mma16816h(float* c, const uint32_t* a, const uint32_t* b) {
    asm volatile(
        "mma.sync.aligned.m16n8k16.row.col.f32.f16.f16.f32 "
        "{%0,%1,%2,%3}, {%4,%5,%6,%7}, {%8,%9}, {%0,%1,%2,%3};"
        : "+f"(c[0]), "+f"(c[1]), "+f"(c[2]), "+f"(c[3])
        : "r"(a[0]), "r"(a[1]), "r"(a[2]), "r"(a[3]), "r"(b[0]), "r"(b[1]));
}
__device__ __forceinline__ uint32_t packh(float lo, float hi) {
    __half2 h = __floats2half2_rn(lo, hi);
    return *(uint32_t*)&h;
}
#define CP_ASYNC16(sm_u32, gptr) \
    asm volatile("cp.async.cg.shared.global [%0], [%1], 16;" :: "r"(sm_u32), "l"(gptr))
#define CP_COMMIT() asm volatile("cp.async.commit_group;" ::: "memory")
#define CP_WAIT1()  asm volatile("cp.async.wait_group 1;" ::: "memory")
#define CP_WAIT0()  asm volatile("cp.async.wait_group 0;" ::: "memory")

// ---------------------------------------------------------------------------
// Convert kernels
// ---------------------------------------------------------------------------
__global__ void cvt_k(const float* __restrict__ in,
                      __half* __restrict__ out, int n4)
{
    int i = blockIdx.x * blockDim.x + threadIdx.x;
    if (i >= n4) return;
    float4 v = *(const float4*)(in + 4 * (size_t)i);
    uint32_t lo = packh(v.x, v.y), hi = packh(v.z, v.w);
    *(uint2*)(out + 4 * (size_t)i) = make_uint2(lo, hi);
}

// Transpose + round: in [K][N] fp32 -> outT [N][K] fp16
__global__ __launch_bounds__(256) void tsplit_k(const float* __restrict__ in,
                                                __half* __restrict__ outT,
                                                int K, int N)
{
    __shared__ float tile[32][33];
    const int tx = threadIdx.x & 31;
    const int ty = threadIdx.x >> 5;       // 0..7
    const int n0 = blockIdx.x * 32;
    const int k0 = blockIdx.y * 32;
#pragma unroll
    for (int i = 0; i < 4; i++) {
        int kk = ty + 8 * i;
        tile[kk][tx] = in[(size_t)(k0 + kk) * N + n0 + tx];
    }
    __syncthreads();
#pragma unroll
    for (int i = 0; i < 4; i++) {
        int nn = ty + 8 * i;
        outT[(size_t)(n0 + nn) * K + k0 + tx] = __float2half_rn(tile[tx][nn]);
    }
}

// ---------------------------------------------------------------------------
// HMMA fp16 GEMM: C[M,N] = A[M,K] * B^T  (A, B fp16; B [N][K])
// CTA 128x128, 8 warps (warp tile 64x32), KC=64, 3-stage pipeline, 2 CTAs/SM.
// half_out: 1 -> write fp16 (packed u32), 0 -> write fp32.
// ---------------------------------------------------------------------------
#define KC 64
#define NKC (GK / KC)            // 16
#define ROWB 144                 // 64 fp16 = 128B data + 16B pad
#define TILE_SB (128 * ROWB)     // 18432
#define STAGE_SB (2 * TILE_SB)   // A, B = 36864
#define NSTG 3
#define GEMM_SMEM_SZ (NSTG * STAGE_SB)  // 110592

__global__ __launch_bounds__(256, 2) void gemm_hmma_k(
    const __half* __restrict__ ah,
    const __half* __restrict__ bT,
    void* __restrict__ Cout, int N, int half_out)
{
    extern __shared__ char sm[];
    const uint32_t sb = smem_to_u32(sm);
    const int t = threadIdx.x;
    const int lane = t & 31;
    const int wid = t >> 5;
    const int wm = wid & 1;          // 2 m-blocks of 64
    const int wn = wid >> 1;         // 4 n-blocks of 32
    const size_t arow0 = (size_t)blockIdx.y * 128;
    const size_t brow0 = (size_t)blockIdx.x * 128;

    const __half* gsrc[2] = { ah + arow0 * GK, bT + brow0 * GK };

    auto issue_stage = [&](int c) {
        const uint32_t st = sb + (uint32_t)(c % NSTG) * STAGE_SB;
        const size_t k0 = (size_t)c * KC;
#pragma unroll
        for (int comp = 0; comp < 2; comp++) {
#pragma unroll
            for (int i = 0; i < 4; i++) {
                int u = t + i * 256;
                int r = u >> 3, ch = u & 7;
                const void* g = gsrc[comp] + (size_t)r * GK + k0 + ch * 8;
                CP_ASYNC16(st + comp * TILE_SB + r * ROWB + ch * 16, g);
            }
        }
    };

    float acc[4][4][4];
#pragma unroll
    for (int mt = 0; mt < 4; mt++)
#pragma unroll
        for (int nt = 0; nt < 4; nt++)
#pragma unroll
            for (int i = 0; i < 4; i++) acc[mt][nt][i] = 0.f;

    issue_stage(0); CP_COMMIT();
    issue_stage(1); CP_COMMIT();
    CP_WAIT1();
    __syncthreads();

    const int idx = lane & 7;
    const int sel = lane >> 3;

    for (int c = 0; c < NKC; c++) {
        if (c + 2 < NKC) issue_stage(c + 2);
        CP_COMMIT();
        const uint32_t st = sb + (uint32_t)(c % NSTG) * STAGE_SB;

#pragma unroll
        for (int j = 0; j < 4; j++) {           // four k16 steps per KC=64
            uint32_t af[4][4], bf[4][2];
            const uint32_t acol = (uint32_t)((2 * j + (sel >> 1)) << 4);
#pragma unroll
            for (int mt = 0; mt < 4; mt++) {
                uint32_t ra = (uint32_t)(wm * 64 + mt * 16 + ((sel & 1) << 3) + idx);
                ldsm4(af[mt], st + ra * ROWB + acol);
            }
            {
                const uint32_t bcol = (uint32_t)((2 * j + (sel & 1)) << 4);
                uint32_t rb = (uint32_t)(wn * 32 + ((sel >> 1) << 3) + idx);
                uint32_t bd = st + TILE_SB + rb * ROWB + bcol;
                uint32_t tmp[4];
                ldsm4(tmp, bd);
                bf[0][0] = tmp[0]; bf[0][1] = tmp[1];
                bf[1][0] = tmp[2]; bf[1][1] = tmp[3];
                ldsm4(tmp, bd + 16 * ROWB);
                bf[2][0] = tmp[0]; bf[2][1] = tmp[1];
                bf[3][0] = tmp[2]; bf[3][1] = tmp[3];
            }
#pragma unroll
            for (int mt = 0; mt < 4; mt++)
#pragma unroll
                for (int nt = 0; nt < 4; nt++)
                    mma16816h(acc[mt][nt], af[mt], bf[nt]);
        }
        CP_WAIT1();
        __syncthreads();
    }

    const int g = lane >> 2, tg = lane & 3;
    if (half_out) {
        __half* C = (__half*)Cout;
#pragma unroll
        for (int mt = 0; mt < 4; mt++) {
            size_t row0 = arow0 + wm * 64 + mt * 16 + g;
#pragma unroll
            for (int nt = 0; nt < 4; nt++) {
                size_t col = brow0 + wn * 32 + nt * 8 + tg * 2;
                *(uint32_t*)(C + row0 * N + col) = packh(acc[mt][nt][0], acc[mt][nt][1]);
                *(uint32_t*)(C + (row0 + 8) * N + col) = packh(acc[mt][nt][2], acc[mt][nt][3]);
            }
        }
    } else {
        float* C = (float*)Cout;
#pragma unroll
        for (int mt = 0; mt < 4; mt++) {
            size_t row0 = arow0 + wm * 64 + mt * 16 + g;
#pragma unroll
            for (int nt = 0; nt < 4; nt++) {
                size_t col = brow0 + wn * 32 + nt * 8 + tg * 2;
                *(float2*)(C + row0 * N + col) = make_float2(acc[mt][nt][0], acc[mt][nt][1]);
                *(float2*)(C + (row0 + 8) * N + col) = make_float2(acc[mt][nt][2], acc[mt][nt][3]);
            }
        }
    }
}

// ---------------------------------------------------------------------------
// RoPE + round: reads g_qkvh (fp16), rotates q (scaled) and k, writes fp16 in
// flash layout [bh][S][64]. Thread handles 2 adjacent i (u32 stores).
// ---------------------------------------------------------------------------
__global__ void ropesplit_k(const int* __restrict__ pos)
{
    int idx = blockIdx.x * blockDim.x + threadIdx.x;
    const int total = ROWS * HH * 2 * 16;
    if (idx >= total) return;
    int i2 = (idx & 15) * 2;           // 0,2,..,30
    int rest = idx >> 4;
    int comp = rest & 1; rest >>= 1;   // 0 = q, 1 = k
    int h = rest & 15;
    int row = rest >> 4;
    int b = row >> 11;                 // / SS
    int s = row & (SS - 1);
    int bh = b * HH + h;

    float p = (float)pos[row];
    const __half* base = g_qkvh + (size_t)row * (3 * DD) + h * TRIPLE + comp * HD;
    float2 x1 = __half22float2(*(const __half2*)(base + i2));
    float2 x2 = __half22float2(*(const __half2*)(base + i2 + 32));

    float o1a, o2a, o1b, o2b;
    {
        float inv = powf(10000.0f, -(float)i2 * (1.0f / 32.0f));
        float sn, cs; sincosf(p * inv, &sn, &cs);
        o1a = x1.x * cs - x2.x * sn;
        o2a = x1.x * sn + x2.x * cs;
    }
    {
        float inv = powf(10000.0f, -(float)(i2 + 1) * (1.0f / 32.0f));
        float sn, cs; sincosf(p * inv, &sn, &cs);
        o1b = x1.y * cs - x2.y * sn;
        o2b = x1.y * sn + x2.y * cs;
    }
    if (comp == 0) { o1a *= 0.125f; o2a *= 0.125f; o1b *= 0.125f; o2b *= 0.125f; }

    __half* dh = (comp ? g_kh : g_qh) + ((size_t)bh * SS + s) * HD;
    *(uint32_t*)(dh + i2)      = packh(o1a, o1b);
    *(uint32_t*)(dh + i2 + 32) = packh(o2a, o2b);
}

// ---------------------------------------------------------------------------
// V transpose: g_qkvh v-part (fp16) -> g_vt [bh][64][S] fp16
// ---------------------------------------------------------------------------
__global__ __launch_bounds__(256) void vsplit_k()
{
    __shared__ float tile[64][65];
    const int bh = blockIdx.x;
    const int b = bh >> 4, h = bh & 15;
    const int s0 = blockIdx.y * 64;
    const int t = threadIdx.x;
#pragma unroll
    for (int i = 0; i < 16; i++) {
        int u = t + i * 256;
        int sl = u >> 6, d = u & 63;
        tile[sl][d] = __half2float(
            g_qkvh[(size_t)(b * SS + s0 + sl) * (3 * DD) + h * TRIPLE + 2 * HD + d]);
    }
    __syncthreads();
#pragma unroll
    for (int i = 0; i < 8; i++) {
        int u = t + i * 256;
        int dl = u >> 5, sl2 = (u & 31) * 2;
        uint32_t v = packh(tile[sl2][dl], tile[sl2 + 1][dl]);
        *(uint32_t*)(g_vt + ((size_t)bh * HD + dl) * SS + s0 + sl2) = v;
    }
}

// ---------------------------------------------------------------------------
// HMMA causal flash attention — fp16, FKT=128 (two 64-key halves per buffer).
// grid (S/128, BH), 256 threads (8 warps, warp = m16 q-tile).
// ---------------------------------------------------------------------------
#define FQ 128
#define FKT 128
#define FSQ 0
#define FSKV 16384
#define FBUF 32768                 // K 16KB + V 2x8KB
#define FLASH_SMEM (16384 + 2 * FBUF)  // 81920

__device__ __forceinline__ uint32_t fsw(int r, int c) {
    return (uint32_t)((r << 7) + (((c ^ (r & 7))) << 4));
}

__global__ __launch_bounds__(256) void flashmma_k()
{
    extern __shared__ char sm[];
    const uint32_t sb = smem_to_u32(sm);
    const int t = threadIdx.x, lane = t & 31, w = t >> 5;
    const int idx = lane & 7, sel = lane >> 3;
    const int bh = blockIdx.y, b = bh >> 4, h = bh & 15;
    const int qt = (int)gridDim.x - 1 - (int)blockIdx.x;   // heavy tiles first
    const int q0 = qt * FQ;
    const int qw = q0 + w * 16;
    const int nbuf = qt + 1;           // 128-key buffers covering 0..q0+127

    // Q tile cp.async
    {
        const __half* s0 = g_qh + ((size_t)bh * SS + q0) * HD;
#pragma unroll
        for (int i = 0; i < 4; i++) {
            int u = t + i * 256; int r = u >> 3, c = u & 7;
            CP_ASYNC16(sb + FSQ + fsw(r, c), s0 + (size_t)r * HD + c * 8);
        }
        CP_COMMIT();
    }

    // load one 128-key buffer: K [128 rows x 128B], V^T two 64x128B sub-tiles
    auto ld_kv = [&](int ct) {
        const int k0 = ct * FKT;
        const uint32_t bd = sb + FSKV + (ct & 1) * FBUF;
        const __half* sk = g_kh + ((size_t)bh * SS + k0) * HD;
#pragma unroll
        for (int i = 0; i < 4; i++) {
            int u = t + i * 256; int r = u >> 3, c = u & 7;
            CP_ASYNC16(bd + fsw(r, c), sk + (size_t)r * HD + c * 8);
        }
        const __half* sv = g_vt + (size_t)bh * HD * SS + k0;
#pragma unroll
        for (int i = 0; i < 4; i++) {
            int u = t + i * 256;
            int r = u >> 4, c = u & 15;        // r: dim 0..63, c: key-chunk 0..15
            uint32_t dst = bd + 16384 + ((c >= 8) ? 8192 : 0) + fsw(r, c & 7);
            CP_ASYNC16(dst, sv + (size_t)r * SS + c * 8);
        }
        CP_COMMIT();
    };

    ld_kv(0);
    CP_WAIT0();
    __syncthreads();

    // Q fragments (resident): 4 k16 chunks
    uint32_t qf[4][4];
#pragma unroll
    for (int j = 0; j < 4; j++) {
        int row = w * 16 + ((sel & 1) << 3) + idx;
        int ch = 2 * j + (sel >> 1);
        ldsm4(qf[j], sb + FSQ + fsw(row, ch));
    }

    float o[8][4];
#pragma unroll
    for (int nt = 0; nt < 8; nt++)
#pragma unroll
        for (int i = 0; i < 4; i++) o[nt][i] = 0.f;
    float m0 = -INFINITY, m1 = -INFINITY, l0 = 0.f, l1 = 0.f;
    const int r = lane >> 2, cb = (lane & 3) * 2;

    for (int cc = 0; cc < nbuf; cc++) {
        if (cc + 1 < nbuf) ld_kv(cc + 1);
        const uint32_t bd = sb + FSKV + (cc & 1) * FBUF;

#pragma unroll
        for (int half = 0; half < 2; half++) {
            const int k0 = cc * FKT + half * 64;
            const uint32_t kbK = bd + half * 8192;
            const uint32_t kbV = bd + 16384 + half * 8192;
            if (k0 > qw + 15) continue;

            float s[8][4];
#pragma unroll
            for (int nt = 0; nt < 8; nt++)
#pragma unroll
                for (int i = 0; i < 4; i++) s[nt][i] = 0.f;

            // S = Q K^T
#pragma unroll
            for (int j = 0; j < 4; j++) {
                const int krow = ((sel >> 1) << 3) + idx;
                const int kch = 2 * j + (sel & 1);
#pragma unroll
                for (int np = 0; np < 4; np++) {
                    uint32_t th[4];
                    ldsm4(th, kbK + fsw(np * 16 + krow, kch));
                    uint32_t b0[2] = { th[0], th[1] }, b1[2] = { th[2], th[3] };
                    mma16816h(s[2 * np],     qf[j], b0);
                    mma16816h(s[2 * np + 1], qf[j], b1);
                }
            }
            // causal mask
            if (k0 + 63 > qw) {
                const int row0 = qw + r, row1 = row0 + 8;
#pragma unroll
                for (int nt = 0; nt < 8; nt++) {
                    int c0 = k0 + nt * 8 + cb;
                    if (c0 > row0)     s[nt][0] = -INFINITY;
                    if (c0 + 1 > row0) s[nt][1] = -INFINITY;
                    if (c0 > row1)     s[nt][2] = -INFINITY;
                    if (c0 + 1 > row1) s[nt][3] = -INFINITY;
                }
            }
            // online softmax
            float mx0 = s[0][0], mx1 = s[0][2];
#pragma unroll
            for (int nt = 0; nt < 8; nt++) {
                mx0 = fmaxf(mx0, fmaxf(s[nt][0], s[nt][1]));
                mx1 = fmaxf(mx1, fmaxf(s[nt][2], s[nt][3]));
            }
            mx0 = fmaxf(mx0, __shfl_xor_sync(0xffffffffu, mx0, 1));
            mx0 = fmaxf(mx0, __shfl_xor_sync(0xffffffffu, mx0, 2));
            mx1 = fmaxf(mx1, __shfl_xor_sync(0xffffffffu, mx1, 1));
            mx1 = fmaxf(mx1, __shfl_xor_sync(0xffffffffu, mx1, 2));
            float mn0 = fmaxf(m0, mx0), mn1 = fmaxf(m1, mx1);
            float sc0 = __expf(m0 - mn0), sc1 = __expf(m1 - mn1);
            float rs0 = 0.f, rs1 = 0.f;
#pragma unroll
            for (int nt = 0; nt < 8; nt++) {
                s[nt][0] = __expf(s[nt][0] - mn0); rs0 += s[nt][0];
                s[nt][1] = __expf(s[nt][1] - mn0); rs0 += s[nt][1];
                s[nt][2] = __expf(s[nt][2] - mn1); rs1 += s[nt][2];
                s[nt][3] = __expf(s[nt][3] - mn1); rs1 += s[nt][3];
            }
            rs0 += __shfl_xor_sync(0xffffffffu, rs0, 1);
            rs0 += __shfl_xor_sync(0xffffffffu, rs0, 2);
            rs1 += __shfl_xor_sync(0xffffffffu, rs1, 1);
            rs1 += __shfl_xor_sync(0xffffffffu, rs1, 2);
            m0 = mn0; m1 = mn1;
            l0 = l0 * sc0 + rs0; l1 = l1 * sc1 + rs1;
#pragma unroll
            for (int nt = 0; nt < 8; nt++) {
                o[nt][0] *= sc0; o[nt][1] *= sc0;
                o[nt][2] *= sc1; o[nt][3] *= sc1;
            }
            // O += P V (single fp16 P)
#pragma unroll
            for (int j = 0; j < 4; j++) {
                uint32_t pa[4];
                pa[0] = packh(s[2 * j][0],     s[2 * j][1]);
                pa[1] = packh(s[2 * j][2],     s[2 * j][3]);
                pa[2] = packh(s[2 * j + 1][0], s[2 * j + 1][1]);
                pa[3] = packh(s[2 * j + 1][2], s[2 * j + 1][3]);
                const int vrow = ((sel >> 1) << 3) + idx;
                const int vch = 2 * j + (sel & 1);
#pragma unroll
                for (int np = 0; np < 4; np++) {
                    uint32_t th[4];
                    ldsm4(th, kbV + fsw(np * 16 + vrow, vch));
                    uint32_t b0[2] = { th[0], th[1] }, b1[2] = { th[2], th[3] };
                    mma16816h(o[2 * np],     pa, b0);
                    mma16816h(o[2 * np + 1], pa, b1);
                }
            }
        }
        __syncthreads();
        if (cc + 1 < nbuf) { CP_WAIT0(); __syncthreads(); }
    }

    // epilogue: normalize, round to fp16, write g_ch [row][h*64+d]
    float i0 = 1.f / l0, i1 = 1.f / l1;
    const size_t row0 = (size_t)b * SS + qw + r;
    const size_t row1 = row0 + 8;
#pragma unroll
    for (int nt = 0; nt < 8; nt++) {
        int col = h * HD + nt * 8 + cb;
        *(uint32_t*)(g_ch + row0 * DD + col) = packh(o[nt][0] * i0, o[nt][1] * i0);
        *(uint32_t*)(g_ch + row1 * DD + col) = packh(o[nt][2] * i1, o[nt][3] * i1);
    }
}

// ---------------------------------------------------------------------------
// Launch
// Inputs: 0=inputs f32[B,S,D], 1=segment_positions i32[B,S], 2=mask (unused),
// 3=W_in f32[D,3D], 4=W_out f32[D,D]. Output: f32[B,S,D].
// ---------------------------------------------------------------------------
extern "C" void kernel_launch(void* const* d_in, const int* in_sizes, int n_in,
                              void* d_out, int out_size)
{
    const float* x    = (const float*)d_in[0];
    const int*   pos  = (const int*)d_in[1];
    const float* Win  = (const float*)d_in[3];
    const float* Wout = (const float*)d_in[4];
    float* out = (float*)d_out;

    __half *qkvh, *ah, *ch, *wT, *oT;
    cudaGetSymbolAddress((void**)&qkvh, g_qkvh);
    cudaGetSymbolAddress((void**)&ah, g_ah);
    cudaGetSymbolAddress((void**)&ch, g_ch);
    cudaGetSymbolAddress((void**)&wT, g_wT);
    cudaGetSymbolAddress((void**)&oT, g_oT);

    cudaFuncSetAttribute(gemm_hmma_k,
                         cudaFuncAttributeMaxDynamicSharedMemorySize, GEMM_SMEM_SZ);
    cudaFuncSetAttribute(flashmma_k,
                         cudaFuncAttributeMaxDynamicSharedMemorySize, FLASH_SMEM);

    // 0) round inputs to fp16; transpose+round weights to fp16
    {
        int n4 = ROWS * DD / 4;
        cvt_k<<<(n4 + 255) / 256, 256>>>(x, ah, n4);
    }
    tsplit_k<<<dim3(3 * DD / 32, DD / 32), 256>>>(Win, wT, DD, 3 * DD);
    tsplit_k<<<dim3(DD / 32, DD / 32), 256>>>(Wout, oT, DD, DD);

    // 1) QKV projection via fp16 HMMA -> fp16 qkv
    gemm_hmma_k<<<dim3(3 * DD / 128, ROWS / 128), 256, GEMM_SMEM_SZ>>>(
        ah, wT, qkvh, 3 * DD, 1);

    // 2) RoPE into flash layouts; V transpose
    {
        int nrope = ROWS * HH * 2 * 16;
        ropesplit_k<<<(nrope + 255) / 256, 256>>>(pos);
    }
    vsplit_k<<<dim3(BB * HH, SS / 64), 256>>>();

    // 3) HMMA causal flash attention (FKT=128; writes fp16 g_ch)
    flashmma_k<<<dim3(SS / FQ, BB * HH), 256, FLASH_SMEM>>>();

    // 4) Output projection via fp16 HMMA -> fp32 out
    gemm_hmma_k<<<dim3(DD / 128, ROWS / 128), 256, GEMM_SMEM_SZ>>>(
        ch, oT, out, DD, 0);
}

// round 13
// speedup vs baseline: 1.0303x; 1.0303x over previous
#include <cuda_runtime.h>
#include <cuda_bf16.h>
#include <cuda_fp16.h>
#include <math.h>
#include <stdint.h>

#define BB 2
#define SS 2048
#define DD 1024
#define HH 16
#define HD 64
#define ROWS (BB*SS)      // 4096
#define TRIPLE (3*HD)     // 192 halves per (row, head)
#define GK 1024           // GEMM K dim (fixed)

// ---------------------------------------------------------------------------
// Scratch (static device globals; no allocation at runtime)
// ---------------------------------------------------------------------------
__device__ __half g_qkvh[(size_t)ROWS * 3 * DD];      // fused qkv fp16 [row][3072]
__device__ __half g_ah[(size_t)ROWS * DD];            // inputs fp16 [row][K]
__device__ __half g_ch[(size_t)ROWS * DD];            // attn out fp16 [row][D]
__device__ __half g_wT[(size_t)3 * DD * DD];          // W_in^T fp16 [3072][1024]
__device__ __half g_oT[(size_t)DD * DD];              // W_out^T fp16 [1024][1024]
// flash operands (fp16): Q,K [bh][S][64]; V^T [bh][64][S]
__device__ __half g_qh[(size_t)BB * HH * SS * HD];
__device__ __half g_kh[(size_t)BB * HH * SS * HD];
__device__ __half g_vt[(size_t)BB * HH * HD * SS];

// ---------------------------------------------------------------------------
// PTX helpers (portable: mma.sync / ldmatrix / cp.async — no arch-'a' features)
// ---------------------------------------------------------------------------
__device__ __forceinline__ uint32_t smem_to_u32(const void* smem_ptr) {
    uint32_t addr;
    asm("{ .reg .u64 tmp; cvta.to.shared.u64 tmp, %1; cvt.u32.u64 %0, tmp; }"
        : "=r"(addr) : "l"(smem_ptr));
    return addr;
}
__device__ __forceinline__ void ldsm4(uint32_t* r, uint32_t addr) {
    asm volatile("ldmatrix.sync.aligned.m8n8.x4.shared.b16 {%0,%1,%2,%3}, [%4];"
                 : "=r"(r[0]), "=r"(r[1]), "=r"(r[2]), "=r"(r[3]) : "r"(addr));
}
__device__ __forceinline__ void mma16816h(float* c, const uint32_t* a, const uint32_t* b) {
    asm volatile(
        "mma.sync.aligned.m16n8k16.row.col.f32.f16.f16.f32 "
        "{%0,%1,%2,%3}, {%4,%5,%6,%7}, {%8,%9}, {%0,%1,%2,%3};"
        : "+f"(c[0]), "+f"(c[1]), "+f"(c[2]), "+f"(c[3])
        : "r"(a[0]), "r"(a[1]), "r"(a[2]), "r"(a[3]), "r"(b[0]), "r"(b[1]));
}
__device__ __forceinline__ uint32_t packh(float lo, float hi) {
    __half2 h = __floats2half2_rn(lo, hi);
    return *(uint32_t*)&h;
}
#define CP_ASYNC16(sm_u32, gptr) \
    asm volatile("cp.async.cg.shared.global [%0], [%1], 16;" :: "r"(sm_u32), "l"(gptr))
#define CP_COMMIT() asm volatile("cp.async.commit_group;" ::: "memory")
#define CP_WAIT1()  asm volatile("cp.async.wait_group 1;" ::: "memory")
#define CP_WAIT0()  asm volatile("cp.async.wait_group 0;" ::: "memory")

// ---------------------------------------------------------------------------
// Fused prep kernel: cvt(x) + transpose/round(W_in) + transpose/round(W_out).
// Block-range dispatch; blocks co-schedule on the chip.
//   [0, 4096)        : cvt inputs  (4 f32 -> 4 fp16 per thread)
//   [4096, 7168)     : tsplit W_in  (N=3072, 96 x-blocks, 32 y-blocks)
//   [7168, 8192)     : tsplit W_out (N=1024, 32 x-blocks, 32 y-blocks)
// ---------------------------------------------------------------------------
__device__ __forceinline__ void tsplit_body(const float* __restrict__ in,
                                            __half* __restrict__ outT,
                                            int K, int N, int bx, int by,
                                            float (*tile)[33])
{
    const int tx = threadIdx.x & 31;
    const int ty = threadIdx.x >> 5;       // 0..7
    const int n0 = bx * 32;
    const int k0 = by * 32;
#pragma unroll
    for (int i = 0; i < 4; i++) {
        int kk = ty + 8 * i;
        tile[kk][tx] = in[(size_t)(k0 + kk) * N + n0 + tx];
    }
    __syncthreads();
#pragma unroll
    for (int i = 0; i < 4; i++) {
        int nn = ty + 8 * i;
        outT[(size_t)(n0 + nn) * K + k0 + tx] = __float2half_rn(tile[tx][nn]);
    }
}

__global__ __launch_bounds__(256) void prep_k(
    const float* __restrict__ x,
    const float* __restrict__ Win,
    const float* __restrict__ Wout,
    __half* __restrict__ ah,
    __half* __restrict__ wT,
    __half* __restrict__ oT)
{
    __shared__ float tile[32][33];
    const int blk = blockIdx.x;
    if (blk < 4096) {
        size_t i = (size_t)blk * 256 + threadIdx.x;     // n4 = 1048576 exactly
        float4 v = *(const float4*)(x + 4 * i);
        uint32_t lo = packh(v.x, v.y), hi = packh(v.z, v.w);
        *(uint2*)(ah + 4 * i) = make_uint2(lo, hi);
    } else if (blk < 7168) {
        int bid = blk - 4096;
        tsplit_body(Win, wT, DD, 3 * DD, bid % 96, bid / 96, tile);
    } else {
        int bid = blk - 7168;
        tsplit_body(Wout, oT, DD, DD, bid % 32, bid / 32, tile);
    }
}

// ---------------------------------------------------------------------------
// HMMA fp16 GEMM: C[M,N] = A[M,K] * B^T  (A, B fp16; B [N][K])
// CTA 128x128, 8 warps (warp tile 64x32), KC=64, 3-stage pipeline, 2 CTAs/SM.
// half_out: 1 -> write fp16 (packed u32), 0 -> write fp32.
// ---------------------------------------------------------------------------
#define KC 64
#define NKC (GK / KC)            // 16
#define ROWB 144                 // 64 fp16 = 128B data + 16B pad
#define TILE_SB (128 * ROWB)     // 18432
#define STAGE_SB (2 * TILE_SB)   // A, B = 36864
#define NSTG 3
#define GEMM_SMEM_SZ (NSTG * STAGE_SB)  // 110592

__global__ __launch_bounds__(256, 2) void gemm_hmma_k(
    const __half* __restrict__ ah,
    const __half* __restrict__ bT,
    void* __restrict__ Cout, int N, int half_out)
{
    extern __shared__ char sm[];
    const uint32_t sb = smem_to_u32(sm);
    const int t = threadIdx.x;
    const int lane = t & 31;
    const int wid = t >> 5;
    const int wm = wid & 1;          // 2 m-blocks of 64
    const int wn = wid >> 1;         // 4 n-blocks of 32
    const size_t arow0 = (size_t)blockIdx.y * 128;
    const size_t brow0 = (size_t)blockIdx.x * 128;

    const __half* gsrc[2] = { ah + arow0 * GK, bT + brow0 * GK };

    auto issue_stage = [&](int c) {
        const uint32_t st = sb + (uint32_t)(c % NSTG) * STAGE_SB;
        const size_t k0 = (size_t)c * KC;
#pragma unroll
        for (int comp = 0; comp < 2; comp++) {
#pragma unroll
            for (int i = 0; i < 4; i++) {
                int u = t + i * 256;
                int r = u >> 3, ch = u & 7;
                const void* g = gsrc[comp] + (size_t)r * GK + k0 + ch * 8;
                CP_ASYNC16(st + comp * TILE_SB + r * ROWB + ch * 16, g);
            }
        }
    };

    float acc[4][4][4];
#pragma unroll
    for (int mt = 0; mt < 4; mt++)
#pragma unroll
        for (int nt = 0; nt < 4; nt++)
#pragma unroll
            for (int i = 0; i < 4; i++) acc[mt][nt][i] = 0.f;

    issue_stage(0); CP_COMMIT();
    issue_stage(1); CP_COMMIT();
    CP_WAIT1();
    __syncthreads();

    const int idx = lane & 7;
    const int sel = lane >> 3;

    for (int c = 0; c < NKC; c++) {
        if (c + 2 < NKC) issue_stage(c + 2);
        CP_COMMIT();
        const uint32_t st = sb + (uint32_t)(c % NSTG) * STAGE_SB;

#pragma unroll
        for (int j = 0; j < 4; j++) {           // four k16 steps per KC=64
            uint32_t af[4][4], bf[4][2];
            const uint32_t acol = (uint32_t)((2 * j + (sel >> 1)) << 4);
#pragma unroll
            for (int mt = 0; mt < 4; mt++) {
                uint32_t ra = (uint32_t)(wm * 64 + mt * 16 + ((sel & 1) << 3) + idx);
                ldsm4(af[mt], st + ra * ROWB + acol);
            }
            {
                const uint32_t bcol = (uint32_t)((2 * j + (sel & 1)) << 4);
                uint32_t rb = (uint32_t)(wn * 32 + ((sel >> 1) << 3) + idx);
                uint32_t bd = st + TILE_SB + rb * ROWB + bcol;
                uint32_t tmp[4];
                ldsm4(tmp, bd);
                bf[0][0] = tmp[0]; bf[0][1] = tmp[1];
                bf[1][0] = tmp[2]; bf[1][1] = tmp[3];
                ldsm4(tmp, bd + 16 * ROWB);
                bf[2][0] = tmp[0]; bf[2][1] = tmp[1];
                bf[3][0] = tmp[2]; bf[3][1] = tmp[3];
            }
#pragma unroll
            for (int mt = 0; mt < 4; mt++)
#pragma unroll
                for (int nt = 0; nt < 4; nt++)
                    mma16816h(acc[mt][nt], af[mt], bf[nt]);
        }
        CP_WAIT1();
        __syncthreads();
    }

    const int g = lane >> 2, tg = lane & 3;
    if (half_out) {
        __half* C = (__half*)Cout;
#pragma unroll
        for (int mt = 0; mt < 4; mt++) {
            size_t row0 = arow0 + wm * 64 + mt * 16 + g;
#pragma unroll
            for (int nt = 0; nt < 4; nt++) {
                size_t col = brow0 + wn * 32 + nt * 8 + tg * 2;
                *(uint32_t*)(C + row0 * N + col) = packh(acc[mt][nt][0], acc[mt][nt][1]);
                *(uint32_t*)(C + (row0 + 8) * N + col) = packh(acc[mt][nt][2], acc[mt][nt][3]);
            }
        }
    } else {
        float* C = (float*)Cout;
#pragma unroll
        for (int mt = 0; mt < 4; mt++) {
            size_t row0 = arow0 + wm * 64 + mt * 16 + g;
#pragma unroll
            for (int nt = 0; nt < 4; nt++) {
                size_t col = brow0 + wn * 32 + nt * 8 + tg * 2;
                *(float2*)(C + row0 * N + col) = make_float2(acc[mt][nt][0], acc[mt][nt][1]);
                *(float2*)(C + (row0 + 8) * N + col) = make_float2(acc[mt][nt][2], acc[mt][nt][3]);
            }
        }
    }
}

// ---------------------------------------------------------------------------
// Fused RoPE + V-transpose kernel (both read g_qkvh only; disjoint outputs).
//   [0, 8192)     : rope (2 adjacent i per thread, u32 stores)
//   [8192, 9216)  : vsplit (bh = bid&31, s-block = bid>>5)
// ---------------------------------------------------------------------------
__global__ __launch_bounds__(256) void ropev_k(const int* __restrict__ pos)
{
    __shared__ float tile[64][65];
    const int blk = blockIdx.x;
    if (blk < 8192) {
        int idx = blk * 256 + threadIdx.x;
        int i2 = (idx & 15) * 2;           // 0,2,..,30
        int rest = idx >> 4;
        int comp = rest & 1; rest >>= 1;   // 0 = q, 1 = k
        int h = rest & 15;
        int row = rest >> 4;
        int b = row >> 11;                 // / SS
        int s = row & (SS - 1);
        int bh = b * HH + h;

        float p = (float)pos[row];
        const __half* base = g_qkvh + (size_t)row * (3 * DD) + h * TRIPLE + comp * HD;
        float2 x1 = __half22float2(*(const __half2*)(base + i2));
        float2 x2 = __half22float2(*(const __half2*)(base + i2 + 32));

        float o1a, o2a, o1b, o2b;
        {
            float inv = powf(10000.0f, -(float)i2 * (1.0f / 32.0f));
            float sn, cs; sincosf(p * inv, &sn, &cs);
            o1a = x1.x * cs - x2.x * sn;
            o2a = x1.x * sn + x2.x * cs;
        }
        {
            float inv = powf(10000.0f, -(float)(i2 + 1) * (1.0f / 32.0f));
            float sn, cs; sincosf(p * inv, &sn, &cs);
            o1b = x1.y * cs - x2.y * sn;
            o2b = x1.y * sn + x2.y * cs;
        }
        if (comp == 0) { o1a *= 0.125f; o2a *= 0.125f; o1b *= 0.125f; o2b *= 0.125f; }

        __half* dh = (comp ? g_kh : g_qh) + ((size_t)bh * SS + s) * HD;
        *(uint32_t*)(dh + i2)      = packh(o1a, o1b);
        *(uint32_t*)(dh + i2 + 32) = packh(o2a, o2b);
    } else {
        int bid = blk - 8192;
        const int bh = bid & 31;
        const int b = bh >> 4, h = bh & 15;
        const int s0 = (bid >> 5) * 64;
        const int t = threadIdx.x;
#pragma unroll
        for (int i = 0; i < 16; i++) {
            int u = t + i * 256;
            int sl = u >> 6, d = u & 63;
            tile[sl][d] = __half2float(
                g_qkvh[(size_t)(b * SS + s0 + sl) * (3 * DD) + h * TRIPLE + 2 * HD + d]);
        }
        __syncthreads();
#pragma unroll
        for (int i = 0; i < 8; i++) {
            int u = t + i * 256;
            int dl = u >> 5, sl2 = (u & 31) * 2;
            uint32_t v = packh(tile[sl2][dl], tile[sl2 + 1][dl]);
            *(uint32_t*)(g_vt + ((size_t)bh * HD + dl) * SS + s0 + sl2) = v;
        }
    }
}

// ---------------------------------------------------------------------------
// HMMA causal flash attention — fp16, FKT=64 (round-11 best-known config).
// grid (S/128, BH), 256 threads (8 warps, warp = m16 q-tile).
// ---------------------------------------------------------------------------
#define FQ 128
#define FKT 64
#define FSQ 0
#define FSKV 16384
#define FBUF 16384
#define FLASH_SMEM 49152

__device__ __forceinline__ uint32_t fsw(int r, int c) {
    return (uint32_t)((r << 7) + (((c ^ (r & 7))) << 4));
}

__global__ __launch_bounds__(256) void flashmma_k()
{
    extern __shared__ char sm[];
    const uint32_t sb = smem_to_u32(sm);
    const int t = threadIdx.x, lane = t & 31, w = t >> 5;
    const int idx = lane & 7, sel = lane >> 3;
    const int bh = blockIdx.y, b = bh >> 4, h = bh & 15;
    const int qt = (int)gridDim.x - 1 - (int)blockIdx.x;   // heavy tiles first
    const int q0 = qt * FQ;
    const int qw = q0 + w * 16;
    const int ntiles = q0 / FKT + 2;

    // Q tile cp.async
    {
        const __half* s0 = g_qh + ((size_t)bh * SS + q0) * HD;
#pragma unroll
        for (int i = 0; i < 4; i++) {
            int u = t + i * 256; int r = u >> 3, c = u & 7;
            CP_ASYNC16(sb + FSQ + fsw(r, c), s0 + (size_t)r * HD + c * 8);
        }
        CP_COMMIT();
    }

    auto ld_kv = [&](int ct) {
        const int k0 = ct * FKT;
        const uint32_t bd = sb + FSKV + (ct & 1) * FBUF;
        const __half* sk = g_kh + ((size_t)bh * SS + k0) * HD;
#pragma unroll
        for (int i = 0; i < 2; i++) {
            int u = t + i * 256; int r = u >> 3, c = u & 7;
            CP_ASYNC16(bd + fsw(r, c), sk + (size_t)r * HD + c * 8);
        }
        const __half* sv = g_vt + (size_t)bh * HD * SS + k0;
#pragma unroll
        for (int i = 0; i < 2; i++) {
            int u = t + i * 256; int r = u >> 3, c = u & 7;
            CP_ASYNC16(bd + 8192 + fsw(r, c), sv + (size_t)r * SS + c * 8);
        }
        CP_COMMIT();
    };

    ld_kv(0);
    CP_WAIT0();
    __syncthreads();

    // Q fragments (resident): 4 k16 chunks
    uint32_t qf[4][4];
#pragma unroll
    for (int j = 0; j < 4; j++) {
        int row = w * 16 + ((sel & 1) << 3) + idx;
        int ch = 2 * j + (sel >> 1);
        ldsm4(qf[j], sb + FSQ + fsw(row, ch));
    }

    float o[8][4];
#pragma unroll
    for (int nt = 0; nt < 8; nt++)
#pragma unroll
        for (int i = 0; i < 4; i++) o[nt][i] = 0.f;
    float m0 = -INFINITY, m1 = -INFINITY, l0 = 0.f, l1 = 0.f;
    const int r = lane >> 2, cb = (lane & 3) * 2;

    for (int c = 0; c < ntiles; c++) {
        if (c + 1 < ntiles) ld_kv(c + 1);
        const int k0 = c * FKT;
        const uint32_t kb = sb + FSKV + (c & 1) * FBUF;

        if (k0 <= qw + 15) {
            float s[8][4];
#pragma unroll
            for (int nt = 0; nt < 8; nt++)
#pragma unroll
                for (int i = 0; i < 4; i++) s[nt][i] = 0.f;

            // S = Q K^T
#pragma unroll
            for (int j = 0; j < 4; j++) {
                const int krow = ((sel >> 1) << 3) + idx;
                const int kch = 2 * j + (sel & 1);
#pragma unroll
                for (int np = 0; np < 4; np++) {
                    uint32_t th[4];
                    ldsm4(th, kb + fsw(np * 16 + krow, kch));
                    uint32_t b0[2] = { th[0], th[1] }, b1[2] = { th[2], th[3] };
                    mma16816h(s[2 * np],     qf[j], b0);
                    mma16816h(s[2 * np + 1], qf[j], b1);
                }
            }
            // causal mask
            if (k0 + FKT - 1 > qw) {
                const int row0 = qw + r, row1 = row0 + 8;
#pragma unroll
                for (int nt = 0; nt < 8; nt++) {
                    int c0 = k0 + nt * 8 + cb;
                    if (c0 > row0)     s[nt][0] = -INFINITY;
                    if (c0 + 1 > row0) s[nt][1] = -INFINITY;
                    if (c0 > row1)     s[nt][2] = -INFINITY;
                    if (c0 + 1 > row1) s[nt][3] = -INFINITY;
                }
            }
            // online softmax
            float mx0 = s[0][0], mx1 = s[0][2];
#pragma unroll
            for (int nt = 0; nt < 8; nt++) {
                mx0 = fmaxf(mx0, fmaxf(s[nt][0], s[nt][1]));
                mx1 = fmaxf(mx1, fmaxf(s[nt][2], s[nt][3]));
            }
            mx0 = fmaxf(mx0, __shfl_xor_sync(0xffffffffu, mx0, 1));
            mx0 = fmaxf(mx0, __shfl_xor_sync(0xffffffffu, mx0, 2));
            mx1 = fmaxf(mx1, __shfl_xor_sync(0xffffffffu, mx1, 1));
            mx1 = fmaxf(mx1, __shfl_xor_sync(0xffffffffu, mx1, 2));
            float mn0 = fmaxf(m0, mx0), mn1 = fmaxf(m1, mx1);
            float sc0 = __expf(m0 - mn0), sc1 = __expf(m1 - mn1);
            float rs0 = 0.f, rs1 = 0.f;
#pragma unroll
            for (int nt = 0; nt < 8; nt++) {
                s[nt][0] = __expf(s[nt][0] - mn0); rs0 += s[nt][0];
                s[nt][1] = __expf(s[nt][1] - mn0); rs0 += s[nt][1];
                s[nt][2] = __expf(s[nt][2] - mn1); rs1 += s[nt][2];
                s[nt][3] = __expf(s[nt][3] - mn1); rs1 += s[nt][3];
            }
            rs0 += __shfl_xor_sync(0xffffffffu, rs0, 1);
            rs0 += __shfl_xor_sync(0xffffffffu, rs0, 2);
            rs1 += __shfl_xor_sync(0xffffffffu, rs1, 1);
            rs1 += __shfl_xor_sync(0xffffffffu, rs1, 2);
            m0 = mn0; m1 = mn1;
            l0 = l0 * sc0 + rs0; l1 = l1 * sc1 + rs1;
#pragma unroll
            for (int nt = 0; nt < 8; nt++) {
                o[nt][0] *= sc0; o[nt][1] *= sc0;
                o[nt][2] *= sc1; o[nt][3] *= sc1;
            }
            // O += P V (single fp16 P)
#pragma unroll
            for (int j = 0; j < 4; j++) {
                uint32_t pa[4];
                pa[0] = packh(s[2 * j][0],     s[2 * j][1]);
                pa[1] = packh(s[2 * j][2],     s[2 * j][3]);
                pa[2] = packh(s[2 * j + 1][0], s[2 * j + 1][1]);
                pa[3] = packh(s[2 * j + 1][2], s[2 * j + 1][3]);
                const int vrow = ((sel >> 1) << 3) + idx;
                const int vch = 2 * j + (sel & 1);
#pragma unroll
                for (int np = 0; np < 4; np++) {
                    uint32_t th[4];
                    ldsm4(th, kb + 8192 + fsw(np * 16 + vrow, vch));
                    uint32_t b0[2] = { th[0], th[1] }, b1[2] = { th[2], th[3] };
                    mma16816h(o[2 * np],     pa, b0);
                    mma16816h(o[2 * np + 1], pa, b1);
                }
            }
        }
        __syncthreads();
        if (c + 1 < ntiles) { CP_WAIT0(); __syncthreads(); }
    }

    // epilogue: normalize, round to fp16, write g_ch [row][h*64+d]
    float i0 = 1.f / l0, i1 = 1.f / l1;
    const size_t row0 = (size_t)b * SS + qw + r;
    const size_t row1 = row0 + 8;
#pragma unroll
    for (int nt = 0; nt < 8; nt++) {
        int col = h * HD + nt * 8 + cb;
        *(uint32_t*)(g_ch + row0 * DD + col) = packh(o[nt][0] * i0, o[nt][1] * i0);
        *(uint32_t*)(g_ch + row1 * DD + col) = packh(o[nt][2] * i1, o[nt][3] * i1);
    }
}

// ---------------------------------------------------------------------------
// Launch
// Inputs: 0=inputs f32[B,S,D], 1=segment_positions i32[B,S], 2=mask (unused),
// 3=W_in f32[D,3D], 4=W_out f32[D,D]. Output: f32[B,S,D].
// ---------------------------------------------------------------------------
extern "C" void kernel_launch(void* const* d_in, const int* in_sizes, int n_in,
                              void* d_out, int out_size)
{
    const float* x    = (const float*)d_in[0];
    const int*   pos  = (const int*)d_in[1];
    const float* Win  = (const float*)d_in[3];
    const float* Wout = (const float*)d_in[4];
    float* out = (float*)d_out;

    __half *qkvh, *ah, *ch, *wT, *oT;
    cudaGetSymbolAddress((void**)&qkvh, g_qkvh);
    cudaGetSymbolAddress((void**)&ah, g_ah);
    cudaGetSymbolAddress((void**)&ch, g_ch);
    cudaGetSymbolAddress((void**)&wT, g_wT);
    cudaGetSymbolAddress((void**)&oT, g_oT);

    cudaFuncSetAttribute(gemm_hmma_k,
                         cudaFuncAttributeMaxDynamicSharedMemorySize, GEMM_SMEM_SZ);
    cudaFuncSetAttribute(flashmma_k,
                         cudaFuncAttributeMaxDynamicSharedMemorySize, FLASH_SMEM);

    // 0) fused prep: cvt inputs + transpose/round both weight matrices
    prep_k<<<8192, 256>>>(x, Win, Wout, ah, wT, oT);

    // 1) QKV projection via fp16 HMMA -> fp16 qkv
    gemm_hmma_k<<<dim3(3 * DD / 128, ROWS / 128), 256, GEMM_SMEM_SZ>>>(
        ah, wT, qkvh, 3 * DD, 1);

    // 2) fused RoPE + V transpose
    ropev_k<<<9216, 256>>>(pos);

    // 3) HMMA causal flash attention (FKT=64; writes fp16 g_ch)
    flashmma_k<<<dim3(SS / FQ, BB * HH), 256, FLASH_SMEM>>>();

    // 4) Output projection via fp16 HMMA -> fp32 out
    gemm_hmma_k<<<dim3(DD / 128, ROWS / 128), 256, GEMM_SMEM_SZ>>>(
        ch, oT, out, DD, 0);
}

// round 15
// speedup vs baseline: 1.0655x; 1.0341x over previous
#include <cuda_runtime.h>
#include <cuda_bf16.h>
#include <cuda_fp16.h>
#include <math.h>
#include <stdint.h>

#define BB 2
#define SS 2048
#define DD 1024
#define HH 16
#define HD 64
#define ROWS (BB*SS)      // 4096
#define TRIPLE (3*HD)     // 192 halves per (row, head)
#define GK 1024           // GEMM K dim (fixed)

// ---------------------------------------------------------------------------
// Scratch (static device globals; no allocation at runtime)
// ---------------------------------------------------------------------------
__device__ __half g_qkvh[(size_t)ROWS * 3 * DD];      // fused qkv fp16 [row][3072]
__device__ __half g_ah[(size_t)ROWS * DD];            // inputs fp16 [row][K]
__device__ __half g_ch[(size_t)ROWS * DD];            // attn out fp16 [row][D]
__device__ __half g_wT[(size_t)3 * DD * DD];          // W_in^T fp16 [3072][1024]
__device__ __half g_oT[(size_t)DD * DD];              // W_out^T fp16 [1024][1024]
// flash operands (fp16): Q,K [bh][S][64]; V^T [bh][64][S]
__device__ __half g_qh[(size_t)BB * HH * SS * HD];
__device__ __half g_kh[(size_t)BB * HH * SS * HD];
__device__ __half g_vt[(size_t)BB * HH * HD * SS];

// ---------------------------------------------------------------------------
// PTX helpers (portable: mma.sync / ldmatrix / cp.async — no arch-'a' features)
// ---------------------------------------------------------------------------
__device__ __forceinline__ uint32_t smem_to_u32(const void* smem_ptr) {
    uint32_t addr;
    asm("{ .reg .u64 tmp; cvta.to.shared.u64 tmp, %1; cvt.u32.u64 %0, tmp; }"
        : "=r"(addr) : "l"(smem_ptr));
    return addr;
}
__device__ __forceinline__ void ldsm4(uint32_t* r, uint32_t addr) {
    asm volatile("ldmatrix.sync.aligned.m8n8.x4.shared.b16 {%0,%1,%2,%3}, [%4];"
                 : "=r"(r[0]), "=r"(r[1]), "=r"(r[2]), "=r"(r[3]) : "r"(addr));
}
__device__ __forceinline__ void mma16816h(float* c, const uint32_t* a, const uint32_t* b) {
    asm volatile(
        "mma.sync.aligned.m16n8k16.row.col.f32.f16.f16.f32 "
        "{%0,%1,%2,%3}, {%4,%5,%6,%7}, {%8,%9}, {%0,%1,%2,%3};"
        : "+f"(c[0]), "+f"(c[1]), "+f"(c[2]), "+f"(c[3])
        : "r"(a[0]), "r"(a[1]), "r"(a[2]), "r"(a[3]), "r"(b[0]), "r"(b[1]));
}
__device__ __forceinline__ uint32_t packh(float lo, float hi) {
    __half2 h = __floats2half2_rn(lo, hi);
    return *(uint32_t*)&h;
}
__device__ __forceinline__ uint32_t h2exp2(uint32_t x) {
    uint32_t d;
    asm("ex2.approx.f16x2 %0, %1;" : "=r"(d) : "r"(x));
    return d;
}
#define CP_ASYNC16(sm_u32, gptr) \
    asm volatile("cp.async.cg.shared.global [%0], [%1], 16;" :: "r"(sm_u32), "l"(gptr))
#define CP_COMMIT() asm volatile("cp.async.commit_group;" ::: "memory")
#define CP_WAIT1()  asm volatile("cp.async.wait_group 1;" ::: "memory")
#define CP_WAIT0()  asm volatile("cp.async.wait_group 0;" ::: "memory")

// ---------------------------------------------------------------------------
// Fused prep kernel: cvt(x) + transpose/round(W_in) + transpose/round(W_out).
// ---------------------------------------------------------------------------
__device__ __forceinline__ void tsplit_body(const float* __restrict__ in,
                                            __half* __restrict__ outT,
                                            int K, int N, int bx, int by,
                                            float (*tile)[33])
{
    const int tx = threadIdx.x & 31;
    const int ty = threadIdx.x >> 5;       // 0..7
    const int n0 = bx * 32;
    const int k0 = by * 32;
#pragma unroll
    for (int i = 0; i < 4; i++) {
        int kk = ty + 8 * i;
        tile[kk][tx] = in[(size_t)(k0 + kk) * N + n0 + tx];
    }
    __syncthreads();
#pragma unroll
    for (int i = 0; i < 4; i++) {
        int nn = ty + 8 * i;
        outT[(size_t)(n0 + nn) * K + k0 + tx] = __float2half_rn(tile[tx][nn]);
    }
}

__global__ __launch_bounds__(256) void prep_k(
    const float* __restrict__ x,
    const float* __restrict__ Win,
    const float* __restrict__ Wout,
    __half* __restrict__ ah,
    __half* __restrict__ wT,
    __half* __restrict__ oT)
{
    __shared__ float tile[32][33];
    const int blk = blockIdx.x;
    if (blk < 4096) {
        size_t i = (size_t)blk * 256 + threadIdx.x;     // n4 = 1048576 exactly
        float4 v = *(const float4*)(x + 4 * i);
        uint32_t lo = packh(v.x, v.y), hi = packh(v.z, v.w);
        *(uint2*)(ah + 4 * i) = make_uint2(lo, hi);
    } else if (blk < 7168) {
        int bid = blk - 4096;
        tsplit_body(Win, wT, DD, 3 * DD, bid % 96, bid / 96, tile);
    } else {
        int bid = blk - 7168;
        tsplit_body(Wout, oT, DD, DD, bid % 32, bid / 32, tile);
    }
}

// ---------------------------------------------------------------------------
// HMMA fp16 GEMM: C[M,N] = A[M,K] * B^T  (A, B fp16; B [N][K])
// CTA 128x128, 8 warps (warp tile 64x32), KC=64, 3-stage pipeline, 2 CTAs/SM.
// ---------------------------------------------------------------------------
#define KC 64
#define NKC (GK / KC)            // 16
#define ROWB 144                 // 64 fp16 = 128B data + 16B pad
#define TILE_SB (128 * ROWB)     // 18432
#define STAGE_SB (2 * TILE_SB)   // A, B = 36864
#define NSTG 3
#define GEMM_SMEM_SZ (NSTG * STAGE_SB)  // 110592

__global__ __launch_bounds__(256, 2) void gemm_hmma_k(
    const __half* __restrict__ ah,
    const __half* __restrict__ bT,
    void* __restrict__ Cout, int N, int half_out)
{
    extern __shared__ char sm[];
    const uint32_t sb = smem_to_u32(sm);
    const int t = threadIdx.x;
    const int lane = t & 31;
    const int wid = t >> 5;
    const int wm = wid & 1;
    const int wn = wid >> 1;
    const size_t arow0 = (size_t)blockIdx.y * 128;
    const size_t brow0 = (size_t)blockIdx.x * 128;

    const __half* gsrc[2] = { ah + arow0 * GK, bT + brow0 * GK };

    auto issue_stage = [&](int c) {
        const uint32_t st = sb + (uint32_t)(c % NSTG) * STAGE_SB;
        const size_t k0 = (size_t)c * KC;
#pragma unroll
        for (int comp = 0; comp < 2; comp++) {
#pragma unroll
            for (int i = 0; i < 4; i++) {
                int u = t + i * 256;
                int r = u >> 3, ch = u & 7;
                const void* g = gsrc[comp] + (size_t)r * GK + k0 + ch * 8;
                CP_ASYNC16(st + comp * TILE_SB + r * ROWB + ch * 16, g);
            }
        }
    };

    float acc[4][4][4];
#pragma unroll
    for (int mt = 0; mt < 4; mt++)
#pragma unroll
        for (int nt = 0; nt < 4; nt++)
#pragma unroll
            for (int i = 0; i < 4; i++) acc[mt][nt][i] = 0.f;

    issue_stage(0); CP_COMMIT();
    issue_stage(1); CP_COMMIT();
    CP_WAIT1();
    __syncthreads();

    const int idx = lane & 7;
    const int sel = lane >> 3;

    for (int c = 0; c < NKC; c++) {
        if (c + 2 < NKC) issue_stage(c + 2);
        CP_COMMIT();
        const uint32_t st = sb + (uint32_t)(c % NSTG) * STAGE_SB;

#pragma unroll
        for (int j = 0; j < 4; j++) {
            uint32_t af[4][4], bf[4][2];
            const uint32_t acol = (uint32_t)((2 * j + (sel >> 1)) << 4);
#pragma unroll
            for (int mt = 0; mt < 4; mt++) {
                uint32_t ra = (uint32_t)(wm * 64 + mt * 16 + ((sel & 1) << 3) + idx);
                ldsm4(af[mt], st + ra * ROWB + acol);
            }
            {
                const uint32_t bcol = (uint32_t)((2 * j + (sel & 1)) << 4);
                uint32_t rb = (uint32_t)(wn * 32 + ((sel >> 1) << 3) + idx);
                uint32_t bd = st + TILE_SB + rb * ROWB + bcol;
                uint32_t tmp[4];
                ldsm4(tmp, bd);
                bf[0][0] = tmp[0]; bf[0][1] = tmp[1];
                bf[1][0] = tmp[2]; bf[1][1] = tmp[3];
                ldsm4(tmp, bd + 16 * ROWB);
                bf[2][0] = tmp[0]; bf[2][1] = tmp[1];
                bf[3][0] = tmp[2]; bf[3][1] = tmp[3];
            }
#pragma unroll
            for (int mt = 0; mt < 4; mt++)
#pragma unroll
                for (int nt = 0; nt < 4; nt++)
                    mma16816h(acc[mt][nt], af[mt], bf[nt]);
        }
        CP_WAIT1();
        __syncthreads();
    }

    const int g = lane >> 2, tg = lane & 3;
    if (half_out) {
        __half* C = (__half*)Cout;
#pragma unroll
        for (int mt = 0; mt < 4; mt++) {
            size_t row0 = arow0 + wm * 64 + mt * 16 + g;
#pragma unroll
            for (int nt = 0; nt < 4; nt++) {
                size_t col = brow0 + wn * 32 + nt * 8 + tg * 2;
                *(uint32_t*)(C + row0 * N + col) = packh(acc[mt][nt][0], acc[mt][nt][1]);
                *(uint32_t*)(C + (row0 + 8) * N + col) = packh(acc[mt][nt][2], acc[mt][nt][3]);
            }
        }
    } else {
        float* C = (float*)Cout;
#pragma unroll
        for (int mt = 0; mt < 4; mt++) {
            size_t row0 = arow0 + wm * 64 + mt * 16 + g;
#pragma unroll
            for (int nt = 0; nt < 4; nt++) {
                size_t col = brow0 + wn * 32 + nt * 8 + tg * 2;
                *(float2*)(C + row0 * N + col) = make_float2(acc[mt][nt][0], acc[mt][nt][1]);
                *(float2*)(C + (row0 + 8) * N + col) = make_float2(acc[mt][nt][2], acc[mt][nt][3]);
            }
        }
    }
}

// ---------------------------------------------------------------------------
// Fused RoPE + V-transpose kernel.
// ---------------------------------------------------------------------------
__global__ __launch_bounds__(256) void ropev_k(const int* __restrict__ pos)
{
    __shared__ float tile[64][65];
    const int blk = blockIdx.x;
    if (blk < 8192) {
        int idx = blk * 256 + threadIdx.x;
        int i2 = (idx & 15) * 2;           // 0,2,..,30
        int rest = idx >> 4;
        int comp = rest & 1; rest >>= 1;   // 0 = q, 1 = k
        int h = rest & 15;
        int row = rest >> 4;
        int b = row >> 11;                 // / SS
        int s = row & (SS - 1);
        int bh = b * HH + h;

        float p = (float)pos[row];
        const __half* base = g_qkvh + (size_t)row * (3 * DD) + h * TRIPLE + comp * HD;
        float2 x1 = __half22float2(*(const __half2*)(base + i2));
        float2 x2 = __half22float2(*(const __half2*)(base + i2 + 32));

        float o1a, o2a, o1b, o2b;
        {
            float inv = powf(10000.0f, -(float)i2 * (1.0f / 32.0f));
            float sn, cs; sincosf(p * inv, &sn, &cs);
            o1a = x1.x * cs - x2.x * sn;
            o2a = x1.x * sn + x2.x * cs;
        }
        {
            float inv = powf(10000.0f, -(float)(i2 + 1) * (1.0f / 32.0f));
            float sn, cs; sincosf(p * inv, &sn, &cs);
            o1b = x1.y * cs - x2.y * sn;
            o2b = x1.y * sn + x2.y * cs;
        }
        if (comp == 0) { o1a *= 0.125f; o2a *= 0.125f; o1b *= 0.125f; o2b *= 0.125f; }

        __half* dh = (comp ? g_kh : g_qh) + ((size_t)bh * SS + s) * HD;
        *(uint32_t*)(dh + i2)      = packh(o1a, o1b);
        *(uint32_t*)(dh + i2 + 32) = packh(o2a, o2b);
    } else {
        int bid = blk - 8192;
        const int bh = bid & 31;
        const int b = bh >> 4, h = bh & 15;
        const int s0 = (bid >> 5) * 64;
        const int t = threadIdx.x;
#pragma unroll
        for (int i = 0; i < 16; i++) {
            int u = t + i * 256;
            int sl = u >> 6, d = u & 63;
            tile[sl][d] = __half2float(
                g_qkvh[(size_t)(b * SS + s0 + sl) * (3 * DD) + h * TRIPLE + 2 * HD + d]);
        }
        __syncthreads();
#pragma unroll
        for (int i = 0; i < 8; i++) {
            int u = t + i * 256;
            int dl = u >> 5, sl2 = (u & 31) * 2;
            uint32_t v = packh(tile[sl2][dl], tile[sl2 + 1][dl]);
            *(uint32_t*)(g_vt + ((size_t)bh * HD + dl) * SS + s0 + sl2) = v;
        }
    }
}

// ---------------------------------------------------------------------------
// HMMA causal flash attention — fp16, FKT=64, fp16x2 softmax (ex2.approx.f16x2).
// grid (S/128, BH), 256 threads (8 warps, warp = m16 q-tile).
// ---------------------------------------------------------------------------
#define FQ 128
#define FKT 64
#define FSQ 0
#define FSKV 16384
#define FBUF 16384
#define FLASH_SMEM 49152

__device__ __forceinline__ uint32_t fsw(int r, int c) {
    return (uint32_t)((r << 7) + (((c ^ (r & 7))) << 4));
}

__global__ __launch_bounds__(256) void flashmma_k()
{
    extern __shared__ char sm[];
    const uint32_t sb = smem_to_u32(sm);
    const int t = threadIdx.x, lane = t & 31, w = t >> 5;
    const int idx = lane & 7, sel = lane >> 3;
    const int bh = blockIdx.y, b = bh >> 4, h = bh & 15;
    const int qt = (int)gridDim.x - 1 - (int)blockIdx.x;   // heavy tiles first
    const int q0 = qt * FQ;
    const int qw = q0 + w * 16;
    const int ntiles = q0 / FKT + 2;
    const float L2E = 1.4426950408889634f;

    // Q tile cp.async
    {
        const __half* s0 = g_qh + ((size_t)bh * SS + q0) * HD;
#pragma unroll
        for (int i = 0; i < 4; i++) {
            int u = t + i * 256; int r = u >> 3, c = u & 7;
            CP_ASYNC16(sb + FSQ + fsw(r, c), s0 + (size_t)r * HD + c * 8);
        }
        CP_COMMIT();
    }

    auto ld_kv = [&](int ct) {
        const int k0 = ct * FKT;
        const uint32_t bd = sb + FSKV + (ct & 1) * FBUF;
        const __half* sk = g_kh + ((size_t)bh * SS + k0) * HD;
#pragma unroll
        for (int i = 0; i < 2; i++) {
            int u = t + i * 256; int r = u >> 3, c = u & 7;
            CP_ASYNC16(bd + fsw(r, c), sk + (size_t)r * HD + c * 8);
        }
        const __half* sv = g_vt + (size_t)bh * HD * SS + k0;
#pragma unroll
        for (int i = 0; i < 2; i++) {
            int u = t + i * 256; int r = u >> 3, c = u & 7;
            CP_ASYNC16(bd + 8192 + fsw(r, c), sv + (size_t)r * SS + c * 8);
        }
        CP_COMMIT();
    };

    ld_kv(0);
    CP_WAIT0();
    __syncthreads();

    // Q fragments (resident): 4 k16 chunks
    uint32_t qf[4][4];
#pragma unroll
    for (int j = 0; j < 4; j++) {
        int row = w * 16 + ((sel & 1) << 3) + idx;
        int ch = 2 * j + (sel >> 1);
        ldsm4(qf[j], sb + FSQ + fsw(row, ch));
    }

    float o[8][4];
#pragma unroll
    for (int nt = 0; nt < 8; nt++)
#pragma unroll
        for (int i = 0; i < 4; i++) o[nt][i] = 0.f;
    float m0 = -INFINITY, m1 = -INFINITY, l0 = 0.f, l1 = 0.f;
    const int r = lane >> 2, cb = (lane & 3) * 2;

    for (int c = 0; c < ntiles; c++) {
        if (c + 1 < ntiles) ld_kv(c + 1);
        const int k0 = c * FKT;
        const uint32_t kb = sb + FSKV + (c & 1) * FBUF;

        if (k0 <= qw + 15) {
            float s[8][4];
#pragma unroll
            for (int nt = 0; nt < 8; nt++)
#pragma unroll
                for (int i = 0; i < 4; i++) s[nt][i] = 0.f;

            // S = Q K^T
#pragma unroll
            for (int j = 0; j < 4; j++) {
                const int krow = ((sel >> 1) << 3) + idx;
                const int kch = 2 * j + (sel & 1);
#pragma unroll
                for (int np = 0; np < 4; np++) {
                    uint32_t th[4];
                    ldsm4(th, kb + fsw(np * 16 + krow, kch));
                    uint32_t b0[2] = { th[0], th[1] }, b1[2] = { th[2], th[3] };
                    mma16816h(s[2 * np],     qf[j], b0);
                    mma16816h(s[2 * np + 1], qf[j], b1);
                }
            }
            // causal mask
            if (k0 + FKT - 1 > qw) {
                const int row0 = qw + r, row1 = row0 + 8;
#pragma unroll
                for (int nt = 0; nt < 8; nt++) {
                    int c0 = k0 + nt * 8 + cb;
                    if (c0 > row0)     s[nt][0] = -INFINITY;
                    if (c0 + 1 > row0) s[nt][1] = -INFINITY;
                    if (c0 > row1)     s[nt][2] = -INFINITY;
                    if (c0 + 1 > row1) s[nt][3] = -INFINITY;
                }
            }
            // online softmax (max in fp32, exp in fp16x2 via ex2.approx.f16x2)
            float mx0 = s[0][0], mx1 = s[0][2];
#pragma unroll
            for (int nt = 0; nt < 8; nt++) {
                mx0 = fmaxf(mx0, fmaxf(s[nt][0], s[nt][1]));
                mx1 = fmaxf(mx1, fmaxf(s[nt][2], s[nt][3]));
            }
            mx0 = fmaxf(mx0, __shfl_xor_sync(0xffffffffu, mx0, 1));
            mx0 = fmaxf(mx0, __shfl_xor_sync(0xffffffffu, mx0, 2));
            mx1 = fmaxf(mx1, __shfl_xor_sync(0xffffffffu, mx1, 1));
            mx1 = fmaxf(mx1, __shfl_xor_sync(0xffffffffu, mx1, 2));
            float mn0 = fmaxf(m0, mx0), mn1 = fmaxf(m1, mx1);
            float sc0 = __expf(m0 - mn0), sc1 = __expf(m1 - mn1);
            const float mnL0 = mn0 * L2E, mnL1 = mn1 * L2E;

            uint32_t ph[8][2];
            float rs0 = 0.f, rs1 = 0.f;
#pragma unroll
            for (int nt = 0; nt < 8; nt++) {
                uint32_t p0 = h2exp2(packh(fmaf(s[nt][0], L2E, -mnL0),
                                           fmaf(s[nt][1], L2E, -mnL0)));
                uint32_t p1 = h2exp2(packh(fmaf(s[nt][2], L2E, -mnL1),
                                           fmaf(s[nt][3], L2E, -mnL1)));
                ph[nt][0] = p0; ph[nt][1] = p1;
                float2 f0 = __half22float2(*(__half2*)&p0);
                float2 f1 = __half22float2(*(__half2*)&p1);
                rs0 += f0.x + f0.y;
                rs1 += f1.x + f1.y;
            }
            rs0 += __shfl_xor_sync(0xffffffffu, rs0, 1);
            rs0 += __shfl_xor_sync(0xffffffffu, rs0, 2);
            rs1 += __shfl_xor_sync(0xffffffffu, rs1, 1);
            rs1 += __shfl_xor_sync(0xffffffffu, rs1, 2);
            m0 = mn0; m1 = mn1;
            l0 = l0 * sc0 + rs0; l1 = l1 * sc1 + rs1;
#pragma unroll
            for (int nt = 0; nt < 8; nt++) {
                o[nt][0] *= sc0; o[nt][1] *= sc0;
                o[nt][2] *= sc1; o[nt][3] *= sc1;
            }
            // O += P V (P pairs straight from fp16x2 exp)
#pragma unroll
            for (int j = 0; j < 4; j++) {
                uint32_t pa[4];
                pa[0] = ph[2 * j][0];
                pa[1] = ph[2 * j][1];
                pa[2] = ph[2 * j + 1][0];
                pa[3] = ph[2 * j + 1][1];
                const int vrow = ((sel >> 1) << 3) + idx;
                const int vch = 2 * j + (sel & 1);
#pragma unroll
                for (int np = 0; np < 4; np++) {
                    uint32_t th[4];
                    ldsm4(th, kb + 8192 + fsw(np * 16 + vrow, vch));
                    uint32_t b0[2] = { th[0], th[1] }, b1[2] = { th[2], th[3] };
                    mma16816h(o[2 * np],     pa, b0);
                    mma16816h(o[2 * np + 1], pa, b1);
                }
            }
        }
        __syncthreads();
        if (c + 1 < ntiles) { CP_WAIT0(); __syncthreads(); }
    }

    // epilogue: normalize, round to fp16, write g_ch [row][h*64+d]
    float i0 = 1.f / l0, i1 = 1.f / l1;
    const size_t row0 = (size_t)b * SS + qw + r;
    const size_t row1 = row0 + 8;
#pragma unroll
    for (int nt = 0; nt < 8; nt++) {
        int col = h * HD + nt * 8 + cb;
        *(uint32_t*)(g_ch + row0 * DD + col) = packh(o[nt][0] * i0, o[nt][1] * i0);
        *(uint32_t*)(g_ch + row1 * DD + col) = packh(o[nt][2] * i1, o[nt][3] * i1);
    }
}

// ---------------------------------------------------------------------------
// Launch
// Inputs: 0=inputs f32[B,S,D], 1=segment_positions i32[B,S], 2=mask (unused),
// 3=W_in f32[D,3D], 4=W_out f32[D,D]. Output: f32[B,S,D].
// ---------------------------------------------------------------------------
extern "C" void kernel_launch(void* const* d_in, const int* in_sizes, int n_in,
                              void* d_out, int out_size)
{
    const float* x    = (const float*)d_in[0];
    const int*   pos  = (const int*)d_in[1];
    const float* Win  = (const float*)d_in[3];
    const float* Wout = (const float*)d_in[4];
    float* out = (float*)d_out;

    __half *qkvh, *ah, *ch, *wT, *oT;
    cudaGetSymbolAddress((void**)&qkvh, g_qkvh);
    cudaGetSymbolAddress((void**)&ah, g_ah);
    cudaGetSymbolAddress((void**)&ch, g_ch);
    cudaGetSymbolAddress((void**)&wT, g_wT);
    cudaGetSymbolAddress((void**)&oT, g_oT);

    cudaFuncSetAttribute(gemm_hmma_k,
                         cudaFuncAttributeMaxDynamicSharedMemorySize, GEMM_SMEM_SZ);
    cudaFuncSetAttribute(flashmma_k,
                         cudaFuncAttributeMaxDynamicSharedMemorySize, FLASH_SMEM);

    // 0) fused prep: cvt inputs + transpose/round both weight matrices
    prep_k<<<8192, 256>>>(x, Win, Wout, ah, wT, oT);

    // 1) QKV projection via fp16 HMMA -> fp16 qkv
    gemm_hmma_k<<<dim3(3 * DD / 128, ROWS / 128), 256, GEMM_SMEM_SZ>>>(
        ah, wT, qkvh, 3 * DD, 1);

    // 2) fused RoPE + V transpose
    ropev_k<<<9216, 256>>>(pos);

    // 3) HMMA causal flash attention (fp16x2 softmax; writes fp16 g_ch)
    flashmma_k<<<dim3(SS / FQ, BB * HH), 256, FLASH_SMEM>>>();

    // 4) Output projection via fp16 HMMA -> fp32 out
    gemm_hmma_k<<<dim3(DD / 128, ROWS / 128), 256, GEMM_SMEM_SZ>>>(
        ch, oT, out, DD, 0);
}